// round 7
// baseline (speedup 1.0000x reference)
#include <cuda_runtime.h>
#include <cstdint>
#include <math.h>

#define NIMG 16
#define NPROP 16384
#define NGT 128
#define M_TOT 16512           // NPROP + NGT
#define KPOS 128
#define KNEG 384
#define NSAMP 512
#define CAP 2048              // per (img, cat) candidate capacity
#define CAPF 4096             // fallback buffer
#define TNEG 7864320u         // 2^23 - 2^19 : neg score window

typedef unsigned long long ull;

// ---------------- scratch ----------------
__device__ unsigned g_rec[NIMG * M_TOT];     // (u23<<1)|is_pos  (fallback only)
__device__ int g_labcl[NIMG * M_TOT];        // label|(cl<<8)    (positives)
__device__ ull g_cand[NIMG * 2 * CAP];
__device__ int g_ccnt[NIMG * 2];

// ---------------- threefry2x32 (jax partitionable path) ----------------
__device__ __forceinline__ unsigned rscore_u(unsigned f) {
    unsigned k0 = 0u, k1 = 42u;
    unsigned ks2 = k0 ^ k1 ^ 0x1BD11BDAu;
    unsigned x0 = 0u, x1 = f;
    x0 += k0; x1 += k1;
#define TF_R(r) { x0 += x1; x1 = (x1 << (r)) | (x1 >> (32 - (r))); x1 ^= x0; }
    TF_R(13) TF_R(15) TF_R(26) TF_R(6)
    x0 += k1; x1 += ks2 + 1u;
    TF_R(17) TF_R(29) TF_R(16) TF_R(24)
    x0 += ks2; x1 += k0 + 2u;
    TF_R(13) TF_R(15) TF_R(26) TF_R(6)
    x0 += k0; x1 += k1 + 3u;
    TF_R(17) TF_R(29) TF_R(16) TF_R(24)
    x0 += k1; x1 += ks2 + 4u;
    TF_R(13) TF_R(15) TF_R(26) TF_R(6)
    x0 += ks2; x1 += k0 + 5u;
#undef TF_R
    return (x0 ^ x1) >> 9;   // 23-bit uniform; score = u * 2^-23 (monotone)
}

__global__ void init_kernel() {
    if (threadIdx.x < NIMG * 2) g_ccnt[threadIdx.x] = 0;
}

// ---------------- kernel A: uniform screen + redo + candidate append ----------------
__global__ void __launch_bounds__(256) prep_kernel(
        const float4* __restrict__ proposals,
        const float4* __restrict__ gt_boxes,
        const int* __restrict__ gt_labels) {
    __shared__ float4 s_gt[NGT];
    __shared__ float  s_area[NGT];
    __shared__ float  s_sa3[NGT];
    __shared__ int    s_lab[NGT];
    __shared__ int    s_flag[1024];
    __shared__ int    s_nflag;

    const int i = blockIdx.y;
    const int t = threadIdx.x;
    const int lane = t & 31;
    if (t == 0) s_nflag = 0;
    if (t < NGT) {
        float4 g = gt_boxes[i * NGT + t];
        s_gt[t] = g;
        float a = __fmul_rn(__fsub_rn(g.z, g.x), __fsub_rn(g.w, g.y));
        s_area[t] = a;
        s_sa3[t] = a * (1.0f / 3.0f);
        s_lab[t] = gt_labels[i * NGT + t];
    }
    __syncthreads();

    const int gi = i * M_TOT;
    const int mb = blockIdx.x * 1024 + t * 4;
    const bool valid = (mb < M_TOT);          // M_TOT % 4 == 0 -> all 4 valid
    unsigned u4[4] = {0u, 0u, 0u, 0u};
    bool fl4[4] = {false, false, false, false};

    if (valid) {
        float4 p0 = (mb + 0 < NPROP) ? proposals[(size_t)i * NPROP + mb + 0] : s_gt[mb + 0 - NPROP];
        float4 p1 = (mb + 1 < NPROP) ? proposals[(size_t)i * NPROP + mb + 1] : s_gt[mb + 1 - NPROP];
        float4 p2 = (mb + 2 < NPROP) ? proposals[(size_t)i * NPROP + mb + 2] : s_gt[mb + 2 - NPROP];
        float4 p3 = (mb + 3 < NPROP) ? proposals[(size_t)i * NPROP + mb + 3] : s_gt[mb + 3 - NPROP];
        float ab0 = __fmul_rn(__fsub_rn(p0.z, p0.x), __fsub_rn(p0.w, p0.y)) * (1.0f / 3.0f);
        float ab1 = __fmul_rn(__fsub_rn(p1.z, p1.x), __fsub_rn(p1.w, p1.y)) * (1.0f / 3.0f);
        float ab2 = __fmul_rn(__fsub_rn(p2.z, p2.x), __fsub_rn(p2.w, p2.y)) * (1.0f / 3.0f);
        float ab3_ = __fmul_rn(__fsub_rn(p3.z, p3.x), __fsub_rn(p3.w, p3.y)) * (1.0f / 3.0f);

        float a0 = -1e30f, a1 = -1e30f, a2 = -1e30f, a3 = -1e30f;

        #pragma unroll 4
        for (int j = 0; j < NGT; j++) {
            float4 g = s_gt[j];                // uniform j -> broadcast LDS
            float sa3 = s_sa3[j];
            // single clamp on wx: no-x-overlap => val = -sa3 (safe; see analysis)
            {
                float wx = fmaxf(__fsub_rn(fminf(g.z, p0.z), fmaxf(g.x, p0.x)), 0.0f);
                float hy = __fsub_rn(fminf(g.w, p0.w), fmaxf(g.y, p0.y));
                a0 = fmaxf(a0, __fmaf_rn(wx, hy, -sa3));
            }
            {
                float wx = fmaxf(__fsub_rn(fminf(g.z, p1.z), fmaxf(g.x, p1.x)), 0.0f);
                float hy = __fsub_rn(fminf(g.w, p1.w), fmaxf(g.y, p1.y));
                a1 = fmaxf(a1, __fmaf_rn(wx, hy, -sa3));
            }
            {
                float wx = fmaxf(__fsub_rn(fminf(g.z, p2.z), fmaxf(g.x, p2.x)), 0.0f);
                float hy = __fsub_rn(fminf(g.w, p2.w), fmaxf(g.y, p2.y));
                a2 = fmaxf(a2, __fmaf_rn(wx, hy, -sa3));
            }
            {
                float wx = fmaxf(__fsub_rn(fminf(g.z, p3.z), fmaxf(g.x, p3.x)), 0.0f);
                float hy = __fsub_rn(fminf(g.w, p3.w), fmaxf(g.y, p3.y));
                a3 = fmaxf(a3, __fmaf_rn(wx, hy, -sa3));
            }
        }

        fl4[0] = (a0 >= ab0 - 1.0f);
        fl4[1] = (a1 >= ab1 - 1.0f);
        fl4[2] = (a2 >= ab2 - 1.0f);
        fl4[3] = (a3 >= ab3_ - 1.0f);

        u4[0] = rscore_u((unsigned)(gi + mb + 0));
        u4[1] = rscore_u((unsigned)(gi + mb + 1));
        u4[2] = rscore_u((unsigned)(gi + mb + 2));
        u4[3] = rscore_u((unsigned)(gi + mb + 3));

        *reinterpret_cast<uint4*>(&g_rec[gi + mb]) =
            make_uint4(u4[0] << 1, u4[1] << 1, u4[2] << 1, u4[3] << 1);

        #pragma unroll
        for (int q = 0; q < 4; q++)
            if (fl4[q]) { int pp = atomicAdd(&s_nflag, 1); s_flag[pp] = mb + q; }
    }

    // neg candidate append (unflagged, windowed) - warp aggregated, full-warp ballots
    #pragma unroll
    for (int q = 0; q < 4; q++) {
        bool pq = valid && !fl4[q] && (u4[q] >= TNEG);
        unsigned msk = __ballot_sync(0xFFFFFFFFu, pq);
        if (msk) {
            int leader = __ffs(msk) - 1;
            int base = 0;
            if (lane == leader) base = atomicAdd(&g_ccnt[i * 2 + 1], __popc(msk));
            base = __shfl_sync(0xFFFFFFFFu, base, leader);
            if (pq) {
                int pos = base + __popc(msk & ((1u << lane) - 1u));
                if (pos < CAP)
                    g_cand[(i * 2 + 1) * CAP + pos] =
                        ((ull)u4[q] << 32) | (unsigned)(~(unsigned)(mb + q));
            }
        }
    }
    __syncthreads();

    // ---- exact redo: one warp per flagged proposal (validated path) ----
    const int nf = s_nflag;
    const int wid = t >> 5;
    for (int e = wid; e < nf; e += 8) {
        const int m = s_flag[e];
        float4 p = (m < NPROP) ? proposals[(size_t)i * NPROP + m] : s_gt[m - NPROP];
        const float ab = __fmul_rn(__fsub_rn(p.z, p.x), __fsub_rn(p.w, p.y));

        float bi, bd; int bj;
        {
            float4 g = s_gt[lane];
            float wx = __fsub_rn(fminf(g.z, p.z), fmaxf(g.x, p.x));
            float hy = __fsub_rn(fminf(g.w, p.w), fmaxf(g.y, p.y));
            bi = __fmul_rn(fmaxf(wx, 0.0f), fmaxf(hy, 0.0f));
            bd = __fsub_rn(__fadd_rn(s_area[lane], ab), bi);
            bj = lane;
        }
        #pragma unroll
        for (int kk = 1; kk < 4; kk++) {
            int j = lane + kk * 32;
            float4 g = s_gt[j];
            float wx = __fsub_rn(fminf(g.z, p.z), fmaxf(g.x, p.x));
            float hy = __fsub_rn(fminf(g.w, p.w), fmaxf(g.y, p.y));
            float inter = __fmul_rn(fmaxf(wx, 0.0f), fmaxf(hy, 0.0f));
            float den = __fsub_rn(__fadd_rn(s_area[j], ab), inter);
            float u = __fmul_rn(inter, bd), v = __fmul_rn(bi, den);
            float eu = __fmaf_rn(inter, bd, -u), ev = __fmaf_rn(bi, den, -v);
            if ((u > v) || (u == v && eu > ev)) { bi = inter; bd = den; bj = j; }
        }
        #pragma unroll
        for (int off = 16; off > 0; off >>= 1) {
            float obi = __shfl_xor_sync(0xFFFFFFFFu, bi, off);
            float obd = __shfl_xor_sync(0xFFFFFFFFu, bd, off);
            int   obj = __shfl_xor_sync(0xFFFFFFFFu, bj, off);
            float u = __fmul_rn(obi, bd), v = __fmul_rn(bi, obd);
            float eu = __fmaf_rn(obi, bd, -u), ev = __fmaf_rn(bi, obd, -v);
            bool gt = (u > v) || (u == v && eu > ev);
            bool eq = (u == v) && (eu == ev);
            if (gt || (eq && obj < bj)) { bi = obi; bd = obd; bj = obj; }
        }
        if (lane == 0) {
            bool pos = __fdiv_rn(bi, bd) >= 0.5f;     // bit-exact threshold
            unsigned u = rscore_u((unsigned)(gi + m));
            g_rec[gi + m] = (u << 1) | (pos ? 1u : 0u);
            if (pos) {
                g_labcl[gi + m] = s_lab[bj] | (bj << 8);
                int p2 = atomicAdd(&g_ccnt[i * 2 + 0], 1);
                if (p2 < CAP)
                    g_cand[(i * 2 + 0) * CAP + p2] = ((ull)u << 32) | (unsigned)(~(unsigned)m);
            } else if (u >= TNEG) {
                int p2 = atomicAdd(&g_ccnt[i * 2 + 1], 1);
                if (p2 < CAP)
                    g_cand[(i * 2 + 1) * CAP + p2] = ((ull)u << 32) | (unsigned)(~(unsigned)m);
            }
        }
    }
}

// ---------------- kernel B: candidate rank-sort + encode ----------------
__global__ void __launch_bounds__(1024) select_kernel(
        const float4* __restrict__ proposals,
        const float4* __restrict__ gt_boxes,
        float* __restrict__ out) {
    __shared__ ull cand[CAPF];
    __shared__ int s_red[32];
    __shared__ int s_bc, s_cc;

    const int i = blockIdx.x;
    const int cat = blockIdx.y;
    const unsigned want = cat ? 0u : 1u;
    const int k = cat ? KNEG : KPOS;
    const int t = threadIdx.x;
    const int lane = t & 31, wid = t >> 5;

    const int cnt = g_ccnt[i * 2 + cat];
    int CC;
    if (cnt >= k && cnt <= CAP) {
        // fast path: candidates already compacted by prep
        for (int c = t; c < cnt; c += 1024)
            cand[c] = g_cand[(i * 2 + cat) * CAP + c];
        CC = cnt;
    } else {
        // exact fallback over g_rec (never taken with this dataset)
        const unsigned* __restrict__ rec = g_rec + (size_t)i * M_TOT;
        unsigned lo = 0, hi = 8388607u;
        while (lo < hi) {
            unsigned mid = (lo + hi + 1) >> 1;
            int c = 0;
            for (int m = t; m < M_TOT; m += 1024) {
                unsigned r = rec[m];
                c += ((r & 1u) == want && (r >> 1) >= mid);
            }
            #pragma unroll
            for (int o = 16; o > 0; o >>= 1) c += __shfl_xor_sync(0xFFFFFFFFu, c, o);
            if (lane == 0) s_red[wid] = c;
            __syncthreads();
            if (t == 0) { int s = 0; for (int w = 0; w < 32; w++) s += s_red[w]; s_bc = s; }
            __syncthreads();
            if (s_bc >= k) lo = mid; else hi = mid - 1;
            __syncthreads();
        }
        if (t == 0) s_cc = 0;
        __syncthreads();
        for (int m = t; m < M_TOT; m += 1024) {
            unsigned r = rec[m];
            if ((r & 1u) == want && (r >> 1) >= lo) {
                int p = atomicAdd(&s_cc, 1);
                if (p < CAPF)
                    cand[p] = ((ull)(r >> 1) << 32) | (unsigned)(~(unsigned)m);
            }
        }
        __syncthreads();
        CC = min(s_cc, CAPF);
    }
    __syncthreads();

    // rank-counting sort (distinct (u,~m) keys) + fused encode
    for (int c = t; c < CC; c += 1024) {
        const ull mykey = cand[c];
        int rnk = 0;
        for (int j = 0; j < CC; j++) rnk += (cand[j] > mykey);
        if (rnk < k) {
            int m = (int)(~(unsigned)(mykey & 0xFFFFFFFFULL));
            int label = 0, cl = 0;
            if (cat == 0) {
                int labcl = g_labcl[(size_t)i * M_TOT + m];
                label = labcl & 0xFF;
                cl = labcl >> 8;
            }
            float4 p = (m < NPROP) ? proposals[(size_t)i * NPROP + m]
                                   : gt_boxes[i * NGT + (m - NPROP)];
            float4 g = gt_boxes[i * NGT + cl];

            float rw = p.z - p.x, rh = p.w - p.y;
            float rcx = p.x + 0.5f * rw, rcy = p.y + 0.5f * rh;
            float gw = g.z - g.x, gh = g.w - g.y;
            float gcx = g.x + 0.5f * gw, gcy = g.y + 0.5f * gh;

            float t0 = 10.0f * __fdiv_rn(gcx - rcx, rw);
            float t1 = 10.0f * __fdiv_rn(gcy - rcy, rh);
            float t2 = 5.0f * logf(__fdiv_rn(gw, rw));
            float t3 = 5.0f * logf(__fdiv_rn(gh, rh));

            int row = i * NSAMP + (cat ? KPOS : 0) + rnk;
            out[row * 4 + 0] = t0;
            out[row * 4 + 1] = t1;
            out[row * 4 + 2] = t2;
            out[row * 4 + 3] = t3;
            out[NIMG * NSAMP * 4 + row] = (float)label;
            out[NIMG * NSAMP * 4 + NIMG * NSAMP + row] = (float)m;
        }
    }
}

// ---------------- launch ----------------
extern "C" void kernel_launch(void* const* d_in, const int* in_sizes, int n_in,
                              void* d_out, int out_size) {
    const float4* proposals = (const float4*)d_in[0];
    const float4* gt_boxes  = (const float4*)d_in[1];
    const int*    gt_labels = (const int*)d_in[2];
    float* out = (float*)d_out;

    init_kernel<<<1, 32>>>();
    prep_kernel<<<dim3((M_TOT + 1023) / 1024, NIMG), 256>>>(proposals, gt_boxes, gt_labels);
    select_kernel<<<dim3(NIMG, 2), 1024>>>(proposals, gt_boxes, out);
}